// round 1
// baseline (speedup 1.0000x reference)
#include <cuda_runtime.h>
#include <math_constants.h>

// Problem constants (fixed by the dataset)
#define QN   2048
#define NN   100000
#define DD   512
#define NPAD 100096          // 782 * 128, row stride for scratch
#define KSEL 32

// Scratch (device globals: no runtime allocation allowed)
__device__ float g_mm[NPAD];
__device__ float g_S[(size_t)QN * NPAD];   // ~820 MB score matrix

// ---------------------------------------------------------------------------
// Packed f32x2 helpers (SASS FFMA2 — reachable only via PTX fma.rn.f32x2)
// ---------------------------------------------------------------------------
__device__ __forceinline__ unsigned long long dup2(float x) {
    unsigned long long r;
    asm("mov.b64 %0, {%1, %1};" : "=l"(r) : "r"(__float_as_uint(x)));
    return r;
}
__device__ __forceinline__ void ffma2(unsigned long long& c,
                                      unsigned long long a,
                                      unsigned long long b) {
    asm("fma.rn.f32x2 %0, %1, %2, %0;" : "+l"(c) : "l"(a), "l"(b));
}

// ---------------------------------------------------------------------------
// Kernel 1: ||m_j||^2, one warp per row
// ---------------------------------------------------------------------------
__global__ void mm_kernel(const float* __restrict__ M) {
    int row  = blockIdx.x * 8 + (threadIdx.x >> 5);
    int lane = threadIdx.x & 31;
    if (row >= NN) return;
    const float4* p = (const float4*)(M + (size_t)row * DD);
    float s = 0.f;
#pragma unroll
    for (int i = 0; i < 4; i++) {
        float4 v = p[lane + 32 * i];
        s += v.x * v.x + v.y * v.y + v.z * v.z + v.w * v.w;
    }
#pragma unroll
    for (int o = 16; o; o >>= 1) s += __shfl_xor_sync(0xffffffffu, s, o);
    if (lane == 0) g_mm[row] = s;
}

// ---------------------------------------------------------------------------
// Kernel 2: S[q][j] = mm[j] - 2 * (q . m_j)
// 128x128 tile, 256 threads, 8x8 per thread, f32x2 packed FMA accumulation
// ---------------------------------------------------------------------------
__global__ void __launch_bounds__(256, 2)
gemm_kernel(const float* __restrict__ A, const float* __restrict__ B) {
    __shared__ float As[16][128];
    __shared__ float Bs[16][132];   // pad: keeps 16B alignment (132*4 = 528 = 33*16)

    const int tid = threadIdx.x;
    const int tx  = tid & 15;       // output column group
    const int ty  = tid >> 4;       // output row group
    const int bx  = blockIdx.x;     // N tile
    const int by  = blockIdx.y;     // Q tile

    // load mapping: thread -> (row lm, k-offset lk), 8 consecutive floats
    const int lm = tid >> 1;
    const int lk = (tid & 1) * 8;
    const float* Ap    = A + ((size_t)(by * 128 + lm)) * DD + lk;
    const int jload    = bx * 128 + lm;
    const float* Bp    = B + (size_t)jload * DD + lk;
    const bool bvalid  = (jload < NN);

    unsigned long long c[8][4];
#pragma unroll
    for (int i = 0; i < 8; i++)
#pragma unroll
        for (int t = 0; t < 4; t++) c[i][t] = 0ULL;

    for (int k0 = 0; k0 < DD; k0 += 16) {
        float4 a0 = *(const float4*)(Ap + k0);
        float4 a1 = *(const float4*)(Ap + k0 + 4);
        float4 b0 = make_float4(0.f, 0.f, 0.f, 0.f), b1 = b0;
        if (bvalid) {
            b0 = *(const float4*)(Bp + k0);
            b1 = *(const float4*)(Bp + k0 + 4);
        }
        __syncthreads();   // previous iteration's compute done
        As[lk + 0][lm] = a0.x; As[lk + 1][lm] = a0.y;
        As[lk + 2][lm] = a0.z; As[lk + 3][lm] = a0.w;
        As[lk + 4][lm] = a1.x; As[lk + 5][lm] = a1.y;
        As[lk + 6][lm] = a1.z; As[lk + 7][lm] = a1.w;
        Bs[lk + 0][lm] = b0.x; Bs[lk + 1][lm] = b0.y;
        Bs[lk + 2][lm] = b0.z; Bs[lk + 3][lm] = b0.w;
        Bs[lk + 4][lm] = b1.x; Bs[lk + 5][lm] = b1.y;
        Bs[lk + 6][lm] = b1.z; Bs[lk + 7][lm] = b1.w;
        __syncthreads();

#pragma unroll
        for (int k = 0; k < 16; k++) {
            float4 af0 = *(const float4*)&As[k][ty * 8];
            float4 af1 = *(const float4*)&As[k][ty * 8 + 4];
            double2 bd0 = *(const double2*)&Bs[k][tx * 8];
            double2 bd1 = *(const double2*)&Bs[k][tx * 8 + 4];
            unsigned long long bq[4] = {
                (unsigned long long)__double_as_longlong(bd0.x),
                (unsigned long long)__double_as_longlong(bd0.y),
                (unsigned long long)__double_as_longlong(bd1.x),
                (unsigned long long)__double_as_longlong(bd1.y)};
            float av[8] = {af0.x, af0.y, af0.z, af0.w,
                           af1.x, af1.y, af1.z, af1.w};
#pragma unroll
            for (int i = 0; i < 8; i++) {
                unsigned long long a2 = dup2(av[i]);
#pragma unroll
                for (int t = 0; t < 4; t++) ffma2(c[i][t], a2, bq[t]);
            }
        }
    }

    // Epilogue: s = mm[j] - 2*dot, store to scratch
    const int jb = bx * 128 + tx * 8;
    const int qb = by * 128 + ty * 8;
    float mmv[8];
#pragma unroll
    for (int t = 0; t < 8; t++) mmv[t] = g_mm[jb + t];
#pragma unroll
    for (int i = 0; i < 8; i++) {
        float* rowp = g_S + (size_t)(qb + i) * NPAD + jb;
        float o[8];
#pragma unroll
        for (int t = 0; t < 4; t++) {
            unsigned long long cc = c[i][t];
            float lo = __uint_as_float((unsigned)(cc & 0xffffffffu));
            float hi = __uint_as_float((unsigned)(cc >> 32));
            o[2 * t]     = mmv[2 * t]     - 2.f * lo;
            o[2 * t + 1] = mmv[2 * t + 1] - 2.f * hi;
        }
        if (jb + 7 < NN) {
            *(float4*)(rowp)     = make_float4(o[0], o[1], o[2], o[3]);
            *(float4*)(rowp + 4) = make_float4(o[4], o[5], o[6], o[7]);
        } else {
#pragma unroll
            for (int t = 0; t < 8; t++)
                if (jb + t < NN) rowp[t] = o[t];
        }
    }
}

// ---------------------------------------------------------------------------
// Kernel 3: warp-per-query top-32 (K == warpsize: one candidate per lane),
// lexicographic (value, index) ordering to match jax.lax.top_k tie-breaking.
// ---------------------------------------------------------------------------
__global__ void select_kernel(const float* __restrict__ tv,
                              float* __restrict__ out) {
    const unsigned FULL = 0xffffffffu;
    int gw   = (blockIdx.x * blockDim.x + threadIdx.x) >> 5;
    int lane = threadIdx.x & 31;
    if (gw >= QN) return;

    const float* row = g_S + (size_t)gw * NPAD;

    float myv = CUDART_INF_F;
    int   myi = 0x7fffffff;
    float curMax = CUDART_INF_F;
    int   curIdx = 0x7fffffff;
    int   maxLane = 0;

    for (int j0 = 0; j0 < NN; j0 += 32) {        // NN % 32 == 0
        float v = row[j0 + lane];
        int   j = j0 + lane;
        bool better = (v < curMax) || (v == curMax && j < curIdx);
        unsigned m = __ballot_sync(FULL, better);
        while (m) {
            int src = __ffs(m) - 1;
            m &= m - 1;
            float vv = __shfl_sync(FULL, v, src);
            int   jj = j0 + src;
            if (vv < curMax || (vv == curMax && jj < curIdx)) {
                if (lane == maxLane) { myv = vv; myi = jj; }
                // recompute warp max (lexicographic, larger wins)
                float rv = myv; int ri = myi;
#pragma unroll
                for (int o = 16; o; o >>= 1) {
                    float ov = __shfl_xor_sync(FULL, rv, o);
                    int   oi = __shfl_xor_sync(FULL, ri, o);
                    if (ov > rv || (ov == rv && oi > ri)) { rv = ov; ri = oi; }
                }
                curMax = rv; curIdx = ri;
                unsigned mb = __ballot_sync(FULL, (myv == curMax) && (myi == curIdx));
                maxLane = __ffs(mb) - 1;
            }
        }
    }

    // gather true_values at the 32 winning indices and average
    float s = tv[myi];
#pragma unroll
    for (int o = 16; o; o >>= 1) s += __shfl_xor_sync(FULL, s, o);
    if (lane == 0) out[gw] = s * (1.0f / KSEL);
}

// ---------------------------------------------------------------------------
extern "C" void kernel_launch(void* const* d_in, const int* in_sizes, int n_in,
                              void* d_out, int out_size) {
    const float* hq = (const float*)d_in[0];   // [2048, 512]
    const float* me = (const float*)d_in[1];   // [100000, 512]
    const float* tv = (const float*)d_in[2];   // [100000]
    float* out = (float*)d_out;                // [2048]

    mm_kernel<<<(NN + 7) / 8, 256>>>(me);

    dim3 grid(NPAD / 128, QN / 128);           // 782 x 16
    gemm_kernel<<<grid, 256>>>(hq, me);

    select_kernel<<<QN / 8, 256>>>(tv, out);   // 256 blocks x 8 warps
}

// round 3
// speedup vs baseline: 1.7221x; 1.7221x over previous
#include <cuda_runtime.h>
#include <cuda_bf16.h>
#include <math_constants.h>
#include <cstdint>

// ---------------------------------------------------------------------------
// Problem constants
// ---------------------------------------------------------------------------
#define QN   2048
#define NN   100000
#define DD   512
#define NPAD 100096          // 782 * 128
#define KSEL 32

// GEMM tiling
#define TILE_M 128
#define TILE_N 128
#define KC     64            // bf16 per K-chunk (128 B rows -> SW128 swizzle)
#define NCHUNK (DD / KC)     // 8
#define STAGES 3

#define TILE_BYTES  16384    // 128 rows x 128 B
#define OFF_AH 0
#define OFF_AL 16384
#define OFF_BH 32768
#define OFF_BL 49152
#define STAGE_BYTES 65536
#define SMEM_TOTAL (STAGES * STAGE_BYTES)   // 196608

// ---------------------------------------------------------------------------
// Scratch (device globals — no runtime allocation allowed)
// ---------------------------------------------------------------------------
__device__ float g_mm[NPAD];                                   // ||m_j||^2 (pad never read by select)
__device__ float g_S[(size_t)QN * NPAD];                       // score matrix (~820 MB)
__device__ __align__(1024) __nv_bfloat16 g_A[2 * QN * DD];     // [hi|lo][2048][512]
__device__ __align__(1024) __nv_bfloat16 g_B[(size_t)2 * NPAD * DD]; // [hi|lo][100096][512]

// ---------------------------------------------------------------------------
// PTX helpers (family-level sm_80+ features only: cp.async, ldmatrix, mma.sync)
// ---------------------------------------------------------------------------
__device__ __forceinline__ uint32_t smem_u32(const void* p) {
    uint32_t a;
    asm("{ .reg .u64 t; cvta.to.shared.u64 t, %1; cvt.u32.u64 %0, t; }"
        : "=r"(a) : "l"(p));
    return a;
}

#define CP_ASYNC16(dst, src) \
    asm volatile("cp.async.cg.shared.global [%0], [%1], 16;" \
                 :: "r"(dst), "l"(src) : "memory")
#define CP_COMMIT() asm volatile("cp.async.commit_group;" ::: "memory")
#define CP_WAIT2()  asm volatile("cp.async.wait_group 2;"  ::: "memory")

#define LDSM4(r, addr) \
    asm volatile("ldmatrix.sync.aligned.m8n8.x4.shared.b16 {%0,%1,%2,%3}, [%4];" \
                 : "=r"((r)[0]), "=r"((r)[1]), "=r"((r)[2]), "=r"((r)[3]) \
                 : "r"(addr))

#define MMA16816(c, a, b0, b1) \
    asm volatile("mma.sync.aligned.m16n8k16.row.col.f32.bf16.bf16.f32 " \
                 "{%0,%1,%2,%3}, {%4,%5,%6,%7}, {%8,%9}, {%0,%1,%2,%3};" \
                 : "+f"((c)[0]), "+f"((c)[1]), "+f"((c)[2]), "+f"((c)[3]) \
                 : "r"((a)[0]), "r"((a)[1]), "r"((a)[2]), "r"((a)[3]), \
                   "r"(b0), "r"(b1))

// ---------------------------------------------------------------------------
// Kernel: fp32 -> (bf16 hi, bf16 lo) split
// ---------------------------------------------------------------------------
__global__ void convertA_kernel(const float* __restrict__ X) {
    int i = blockIdx.x * blockDim.x + threadIdx.x;
    if (i >= QN * (DD / 2)) return;
    float2 x = ((const float2*)X)[i];
    __nv_bfloat16 h0 = __float2bfloat16(x.x);
    __nv_bfloat16 h1 = __float2bfloat16(x.y);
    __nv_bfloat16 l0 = __float2bfloat16(x.x - __bfloat162float(h0));
    __nv_bfloat16 l1 = __float2bfloat16(x.y - __bfloat162float(h1));
    ((__nv_bfloat162*)g_A)[i]             = __nv_bfloat162(h0, h1);
    ((__nv_bfloat162*)(g_A + QN * DD))[i] = __nv_bfloat162(l0, l1);
}

__global__ void convertB_kernel(const float* __restrict__ X) {
    size_t i = (size_t)blockIdx.x * blockDim.x + threadIdx.x;
    if (i >= (size_t)NPAD * (DD / 2)) return;
    size_t row = (i * 2) >> 9;
    float2 x = make_float2(0.f, 0.f);
    if (row < NN) x = ((const float2*)X)[i];
    __nv_bfloat16 h0 = __float2bfloat16(x.x);
    __nv_bfloat16 h1 = __float2bfloat16(x.y);
    __nv_bfloat16 l0 = __float2bfloat16(x.x - __bfloat162float(h0));
    __nv_bfloat16 l1 = __float2bfloat16(x.y - __bfloat162float(h1));
    ((__nv_bfloat162*)g_B)[i]                       = __nv_bfloat162(h0, h1);
    ((__nv_bfloat162*)(g_B + (size_t)NPAD * DD))[i] = __nv_bfloat162(l0, l1);
}

// ---------------------------------------------------------------------------
// Kernel: ||m_j||^2, one warp per row (validated)
// ---------------------------------------------------------------------------
__global__ void mm_kernel(const float* __restrict__ M) {
    int row  = blockIdx.x * 8 + (threadIdx.x >> 5);
    int lane = threadIdx.x & 31;
    if (row >= NN) return;
    const float4* p = (const float4*)(M + (size_t)row * DD);
    float s = 0.f;
#pragma unroll
    for (int i = 0; i < 4; i++) {
        float4 v = p[lane + 32 * i];
        s += v.x * v.x + v.y * v.y + v.z * v.z + v.w * v.w;
    }
#pragma unroll
    for (int o = 16; o; o >>= 1) s += __shfl_xor_sync(0xffffffffu, s, o);
    if (lane == 0) g_mm[row] = s;
}

// ---------------------------------------------------------------------------
// Kernel: bf16x3 GEMM via mma.sync, S[q][j] = mm[j] - 2*dot(q, m_j)
// 128x128 tile, 8 warps (2M x 4N), warp tile 64x32, 3-stage cp.async pipe
// ---------------------------------------------------------------------------
__global__ void __launch_bounds__(256, 1)
gemm_mma() {
    extern __shared__ char smem[];
    const uint32_t sb = smem_u32(smem);
    const int tid  = threadIdx.x;
    const int lane = tid & 31, wid = tid >> 5;
    const int wm   = wid >> 2, wn = wid & 3;     // 2 x 4 warp grid
    const int gm   = blockIdx.x, gn = blockIdx.y;

    // ---- cp.async mapping: thread -> (16B chunk lc, row lr), 4 row-groups
    const int lc = tid & 7;
    const int lr = tid >> 3;                     // 0..31
    const __nv_bfloat16* srcA = g_A + (size_t)(gm * TILE_M + lr) * DD + lc * 8;
    const __nv_bfloat16* srcB = g_B + (size_t)(gn * TILE_N + lr) * DD + lc * 8;
    const uint32_t dsw = (uint32_t)((lc ^ (lr & 7)) * 16) + (uint32_t)lr * 128;

    // ---- ldmatrix lane geometry
    const int l15 = lane & 15, lh = lane >> 4, l7 = lane & 7;
    const uint32_t arow = (uint32_t)(wm * 64 + l15) * 128;   // byte offset in A tile
    const uint32_t brow = (uint32_t)(wn * 32 + l15) * 128;   // byte offset in B tile

    float acc[4][4][4];
#pragma unroll
    for (int f = 0; f < 4; f++)
#pragma unroll
        for (int n = 0; n < 4; n++)
#pragma unroll
            for (int r = 0; r < 4; r++) acc[f][n][r] = 0.f;

    // ---- pipeline
#pragma unroll 1
    for (int s = 0; s < STAGES; s++) {   // prologue: chunks 0..2
        uint32_t s0 = sb + s * STAGE_BYTES + dsw;
        size_t ko = (size_t)s * KC;
#pragma unroll
        for (int p = 0; p < 4; p++) {
            uint32_t d = s0 + p * 32 * 128;
            const __nv_bfloat16* a = srcA + ko + (size_t)p * 32 * DD;
            const __nv_bfloat16* b = srcB + ko + (size_t)p * 32 * DD;
            CP_ASYNC16(d + OFF_AH, a);
            CP_ASYNC16(d + OFF_AL, a + (size_t)QN * DD);
            CP_ASYNC16(d + OFF_BH, b);
            CP_ASYNC16(d + OFF_BL, b + (size_t)NPAD * DD);
        }
        CP_COMMIT();
    }

#pragma unroll 1
    for (int i = 0; i < NCHUNK; i++) {
        CP_WAIT2();
        __syncthreads();

        const int st = i % STAGES;
        const uint32_t aB = sb + st * STAGE_BYTES + OFF_AH + arow;
        const uint32_t bB = sb + st * STAGE_BYTES + OFF_BH + brow;

#pragma unroll
        for (int s = 0; s < 4; s++) {               // 4 k16 slices per chunk
            const uint32_t ksw = (uint32_t)(((2 * s + lh) ^ l7) * 16);
            uint32_t ah[4][4], al[4][4], bh[2][4], bl[2][4];
#pragma unroll
            for (int f = 0; f < 4; f++) {
                LDSM4(ah[f], aB + f * 2048 + ksw);
                LDSM4(al[f], aB + 16384 + f * 2048 + ksw);
            }
#pragma unroll
            for (int g = 0; g < 2; g++) {
                LDSM4(bh[g], bB + g * 2048 + ksw);
                LDSM4(bl[g], bB + 16384 + g * 2048 + ksw);
            }
#pragma unroll
            for (int f = 0; f < 4; f++) {
#pragma unroll
                for (int n = 0; n < 4; n++) {
                    const int g = n >> 1, o = n & 1;
                    MMA16816(acc[f][n], ah[f], bh[g][o], bh[g][o + 2]);
                    MMA16816(acc[f][n], ah[f], bl[g][o], bl[g][o + 2]);
                    MMA16816(acc[f][n], al[f], bh[g][o], bh[g][o + 2]);
                }
            }
        }
        __syncthreads();

        if (i + STAGES < NCHUNK) {                  // refill freed buffer
            uint32_t s0 = sb + st * STAGE_BYTES + dsw;
            size_t ko = (size_t)(i + STAGES) * KC;
#pragma unroll
            for (int p = 0; p < 4; p++) {
                uint32_t d = s0 + p * 32 * 128;
                const __nv_bfloat16* a = srcA + ko + (size_t)p * 32 * DD;
                const __nv_bfloat16* b = srcB + ko + (size_t)p * 32 * DD;
                CP_ASYNC16(d + OFF_AH, a);
                CP_ASYNC16(d + OFF_AL, a + (size_t)QN * DD);
                CP_ASYNC16(d + OFF_BH, b);
                CP_ASYNC16(d + OFF_BL, b + (size_t)NPAD * DD);
            }
        }
        CP_COMMIT();   // empty groups in the tail keep wait_group 2 exact
    }

    // ---- epilogue: S = mm[j] - 2*dot
    const int r0 = gm * TILE_M + wm * 64 + (lane >> 2);
    const int c0 = gn * TILE_N + wn * 32 + (lane & 3) * 2;
#pragma unroll
    for (int n = 0; n < 4; n++) {
        const int j = c0 + n * 8;
        const float m0 = g_mm[j], m1 = g_mm[j + 1];
#pragma unroll
        for (int f = 0; f < 4; f++) {
            float* b0 = g_S + (size_t)(r0 + f * 16) * NPAD + j;
            float* b1 = g_S + (size_t)(r0 + f * 16 + 8) * NPAD + j;
            float2 v0 = make_float2(fmaf(-2.f, acc[f][n][0], m0),
                                    fmaf(-2.f, acc[f][n][1], m1));
            float2 v1 = make_float2(fmaf(-2.f, acc[f][n][2], m0),
                                    fmaf(-2.f, acc[f][n][3], m1));
            *(float2*)b0 = v0;
            *(float2*)b1 = v1;
        }
    }
}

// ---------------------------------------------------------------------------
// Kernel: warp-per-query top-32 + gather + mean (validated; reads j < NN only)
// ---------------------------------------------------------------------------
__global__ void select_kernel(const float* __restrict__ tv,
                              float* __restrict__ out) {
    const unsigned FULL = 0xffffffffu;
    int gw   = (blockIdx.x * blockDim.x + threadIdx.x) >> 5;
    int lane = threadIdx.x & 31;
    if (gw >= QN) return;

    const float* row = g_S + (size_t)gw * NPAD;

    float myv = CUDART_INF_F;
    int   myi = 0x7fffffff;
    float curMax = CUDART_INF_F;
    int   curIdx = 0x7fffffff;
    int   maxLane = 0;

    for (int j0 = 0; j0 < NN; j0 += 32) {
        float v = row[j0 + lane];
        int   j = j0 + lane;
        bool better = (v < curMax) || (v == curMax && j < curIdx);
        unsigned m = __ballot_sync(FULL, better);
        while (m) {
            int src = __ffs(m) - 1;
            m &= m - 1;
            float vv = __shfl_sync(FULL, v, src);
            int   jj = j0 + src;
            if (vv < curMax || (vv == curMax && jj < curIdx)) {
                if (lane == maxLane) { myv = vv; myi = jj; }
                float rv = myv; int ri = myi;
#pragma unroll
                for (int o = 16; o; o >>= 1) {
                    float ov = __shfl_xor_sync(FULL, rv, o);
                    int   oi = __shfl_xor_sync(FULL, ri, o);
                    if (ov > rv || (ov == rv && oi > ri)) { rv = ov; ri = oi; }
                }
                curMax = rv; curIdx = ri;
                unsigned mb = __ballot_sync(FULL, (myv == curMax) && (myi == curIdx));
                maxLane = __ffs(mb) - 1;
            }
        }
    }

    float s = tv[myi];
#pragma unroll
    for (int o = 16; o; o >>= 1) s += __shfl_xor_sync(FULL, s, o);
    if (lane == 0) out[gw] = s * (1.0f / KSEL);
}

// ---------------------------------------------------------------------------
extern "C" void kernel_launch(void* const* d_in, const int* in_sizes, int n_in,
                              void* d_out, int out_size) {
    const float* hq = (const float*)d_in[0];   // [2048, 512]
    const float* me = (const float*)d_in[1];   // [100000, 512]
    const float* tv = (const float*)d_in[2];   // [100000]
    float* out = (float*)d_out;                // [2048]

    convertA_kernel<<<(QN * (DD / 2) + 255) / 256, 256>>>(hq);
    convertB_kernel<<<(int)(((size_t)NPAD * (DD / 2) + 255) / 256), 256>>>(me);
    mm_kernel<<<(NN + 7) / 8, 256>>>(me);

    cudaFuncSetAttribute(gemm_mma, cudaFuncAttributeMaxDynamicSharedMemorySize,
                         SMEM_TOTAL);
    // x-fast over the 16 M-tiles: concurrent CTAs share B tiles in L2
    gemm_mma<<<dim3(QN / TILE_M, NPAD / TILE_N), 256, SMEM_TOTAL>>>();

    select_kernel<<<QN / 8, 256>>>(tv, out);
}

// round 4
// speedup vs baseline: 3.7693x; 2.1888x over previous
#include <cuda_runtime.h>
#include <cuda_bf16.h>
#include <math_constants.h>
#include <cstdint>

// ---------------------------------------------------------------------------
// Problem constants
// ---------------------------------------------------------------------------
#define QN   2048
#define NN   100000
#define DD   512
#define NPAD 100096          // 782 * 128
#define KSEL 32
#define CAND 256             // shortlist size per query (per-lane top-8 x 32)

// GEMM tiling (hi-only bf16)
#define TILE_M 128
#define TILE_N 128
#define KC     64            // bf16 per K-chunk (128 B rows -> SW128 swizzle)
#define NCHUNK (DD / KC)     // 8
#define STAGES 3

#define OFF_AH 0
#define OFF_BH 16384
#define STAGE_BYTES 32768
#define SMEM_TOTAL (STAGES * STAGE_BYTES)   // 98304 -> 2 CTAs/SM

// ---------------------------------------------------------------------------
// Scratch (device globals — no runtime allocation allowed)
// ---------------------------------------------------------------------------
__device__ float g_mm[NPAD];                                   // ||m_j||^2; +INF for j >= NN
__device__ float g_S[(size_t)QN * NPAD];                       // approx score matrix (~820 MB)
__device__ __align__(1024) __nv_bfloat16 g_A[QN * DD];         // hi(bf16) of queries
__device__ __align__(1024) __nv_bfloat16 g_B[(size_t)NPAD * DD]; // hi(bf16) of memory
__device__ float g_cv[(size_t)QN * CAND];                      // shortlist values (unused by rescore, kept for debug)
__device__ int   g_ci[(size_t)QN * CAND];                      // shortlist indices

// ---------------------------------------------------------------------------
// PTX helpers (family-level sm_80+ features only)
// ---------------------------------------------------------------------------
__device__ __forceinline__ uint32_t smem_u32(const void* p) {
    uint32_t a;
    asm("{ .reg .u64 t; cvta.to.shared.u64 t, %1; cvt.u32.u64 %0, t; }"
        : "=r"(a) : "l"(p));
    return a;
}

#define CP_ASYNC16(dst, src) \
    asm volatile("cp.async.cg.shared.global [%0], [%1], 16;" \
                 :: "r"(dst), "l"(src) : "memory")
#define CP_COMMIT() asm volatile("cp.async.commit_group;" ::: "memory")
#define CP_WAIT2()  asm volatile("cp.async.wait_group 2;"  ::: "memory")

#define LDSM4(r, addr) \
    asm volatile("ldmatrix.sync.aligned.m8n8.x4.shared.b16 {%0,%1,%2,%3}, [%4];" \
                 : "=r"((r)[0]), "=r"((r)[1]), "=r"((r)[2]), "=r"((r)[3]) \
                 : "r"(addr))

#define MMA16816(c, a, b0, b1) \
    asm volatile("mma.sync.aligned.m16n8k16.row.col.f32.bf16.bf16.f32 " \
                 "{%0,%1,%2,%3}, {%4,%5,%6,%7}, {%8,%9}, {%0,%1,%2,%3};" \
                 : "+f"((c)[0]), "+f"((c)[1]), "+f"((c)[2]), "+f"((c)[3]) \
                 : "r"((a)[0]), "r"((a)[1]), "r"((a)[2]), "r"((a)[3]), \
                   "r"(b0), "r"(b1))

// ---------------------------------------------------------------------------
// fp32 -> bf16 hi conversion (lo no longer needed: exact rescore downstream)
// ---------------------------------------------------------------------------
__global__ void convertA_kernel(const float* __restrict__ X) {
    int i = blockIdx.x * blockDim.x + threadIdx.x;
    if (i >= QN * (DD / 2)) return;
    float2 x = ((const float2*)X)[i];
    ((__nv_bfloat162*)g_A)[i] =
        __nv_bfloat162(__float2bfloat16(x.x), __float2bfloat16(x.y));
}

__global__ void convertB_kernel(const float* __restrict__ X) {
    size_t i = (size_t)blockIdx.x * blockDim.x + threadIdx.x;
    if (i >= (size_t)NPAD * (DD / 2)) return;
    size_t row = (i * 2) >> 9;
    float2 x = make_float2(0.f, 0.f);
    if (row < NN) x = ((const float2*)X)[i];
    ((__nv_bfloat162*)g_B)[i] =
        __nv_bfloat162(__float2bfloat16(x.x), __float2bfloat16(x.y));
}

// ---------------------------------------------------------------------------
// ||m_j||^2 (fp32 exact); pad rows get +INF so pad scores poison to +INF
// ---------------------------------------------------------------------------
__global__ void mm_kernel(const float* __restrict__ M) {
    int row  = blockIdx.x * 8 + (threadIdx.x >> 5);
    int lane = threadIdx.x & 31;
    if (row >= NPAD) return;
    if (row >= NN) { if (lane == 0) g_mm[row] = CUDART_INF_F; return; }
    const float4* p = (const float4*)(M + (size_t)row * DD);
    float s = 0.f;
#pragma unroll
    for (int i = 0; i < 4; i++) {
        float4 v = p[lane + 32 * i];
        s += v.x * v.x + v.y * v.y + v.z * v.z + v.w * v.w;
    }
#pragma unroll
    for (int o = 16; o; o >>= 1) s += __shfl_xor_sync(0xffffffffu, s, o);
    if (lane == 0) g_mm[row] = s;
}

// ---------------------------------------------------------------------------
// hi-only bf16 GEMM via mma.sync: S[q][j] = mm[j] - 2*dot_hi(q, m_j)
// 128x128 tile, 8 warps (2M x 4N), 3-stage cp.async pipeline, 2 CTAs/SM
// ---------------------------------------------------------------------------
__global__ void __launch_bounds__(256, 2)
gemm_mma() {
    extern __shared__ char smem[];
    const uint32_t sb = smem_u32(smem);
    const int tid  = threadIdx.x;
    const int lane = tid & 31, wid = tid >> 5;
    const int wm   = wid >> 2, wn = wid & 3;     // 2 x 4 warp grid
    const int gm   = blockIdx.x, gn = blockIdx.y;

    // cp.async mapping: thread -> (16B chunk lc, row lr), 4 row-groups
    const int lc = tid & 7;
    const int lr = tid >> 3;                     // 0..31
    const __nv_bfloat16* srcA = g_A + (size_t)(gm * TILE_M + lr) * DD + lc * 8;
    const __nv_bfloat16* srcB = g_B + (size_t)(gn * TILE_N + lr) * DD + lc * 8;
    const uint32_t dsw = (uint32_t)((lc ^ (lr & 7)) * 16) + (uint32_t)lr * 128;

    // ldmatrix lane geometry
    const int l15 = lane & 15, lh = lane >> 4, l7 = lane & 7;
    const uint32_t arow = (uint32_t)(wm * 64 + l15) * 128;
    const uint32_t brow = (uint32_t)(wn * 32 + l15) * 128;

    float acc[4][4][4];
#pragma unroll
    for (int f = 0; f < 4; f++)
#pragma unroll
        for (int n = 0; n < 4; n++)
#pragma unroll
            for (int r = 0; r < 4; r++) acc[f][n][r] = 0.f;

#pragma unroll 1
    for (int s = 0; s < STAGES; s++) {           // prologue
        uint32_t s0 = sb + s * STAGE_BYTES + dsw;
        size_t ko = (size_t)s * KC;
#pragma unroll
        for (int p = 0; p < 4; p++) {
            uint32_t d = s0 + p * 32 * 128;
            CP_ASYNC16(d + OFF_AH, srcA + ko + (size_t)p * 32 * DD);
            CP_ASYNC16(d + OFF_BH, srcB + ko + (size_t)p * 32 * DD);
        }
        CP_COMMIT();
    }

#pragma unroll 1
    for (int i = 0; i < NCHUNK; i++) {
        CP_WAIT2();
        __syncthreads();

        const int st = i % STAGES;
        const uint32_t aB = sb + st * STAGE_BYTES + OFF_AH + arow;
        const uint32_t bB = sb + st * STAGE_BYTES + OFF_BH + brow;

#pragma unroll
        for (int s = 0; s < 4; s++) {            // 4 k16 slices per chunk
            const uint32_t ksw = (uint32_t)(((2 * s + lh) ^ l7) * 16);
            uint32_t ah[4][4], bh[2][4];
#pragma unroll
            for (int f = 0; f < 4; f++) LDSM4(ah[f], aB + f * 2048 + ksw);
#pragma unroll
            for (int g = 0; g < 2; g++) LDSM4(bh[g], bB + g * 2048 + ksw);
#pragma unroll
            for (int f = 0; f < 4; f++)
#pragma unroll
                for (int n = 0; n < 4; n++) {
                    const int g = n >> 1, o = n & 1;
                    MMA16816(acc[f][n], ah[f], bh[g][o], bh[g][o + 2]);
                }
        }
        __syncthreads();

        if (i + STAGES < NCHUNK) {
            uint32_t s0 = sb + st * STAGE_BYTES + dsw;
            size_t ko = (size_t)(i + STAGES) * KC;
#pragma unroll
            for (int p = 0; p < 4; p++) {
                uint32_t d = s0 + p * 32 * 128;
                CP_ASYNC16(d + OFF_AH, srcA + ko + (size_t)p * 32 * DD);
                CP_ASYNC16(d + OFF_BH, srcB + ko + (size_t)p * 32 * DD);
            }
        }
        CP_COMMIT();
    }

    // epilogue: S = mm[j] - 2*dot  (mm[j>=NN] = +INF -> pad scores = +INF)
    const int r0 = gm * TILE_M + wm * 64 + (lane >> 2);
    const int c0 = gn * TILE_N + wn * 32 + (lane & 3) * 2;
#pragma unroll
    for (int n = 0; n < 4; n++) {
        const int j = c0 + n * 8;
        const float m0 = g_mm[j], m1 = g_mm[j + 1];
#pragma unroll
        for (int f = 0; f < 4; f++) {
            float* b0 = g_S + (size_t)(r0 + f * 16) * NPAD + j;
            float* b1 = g_S + (size_t)(r0 + f * 16 + 8) * NPAD + j;
            *(float2*)b0 = make_float2(fmaf(-2.f, acc[f][n][0], m0),
                                       fmaf(-2.f, acc[f][n][1], m1));
            *(float2*)b1 = make_float2(fmaf(-2.f, acc[f][n][2], m0),
                                       fmaf(-2.f, acc[f][n][3], m1));
        }
    }
}

// ---------------------------------------------------------------------------
// Shortlist: one warp/query, per-lane local top-8 (no warp sync in hot loop).
// Union of per-lane top-8 = 256 candidates; contains exact top-32 w.h.p.
// (lex order: smaller value first, ties -> smaller index, matching lax.top_k)
// ---------------------------------------------------------------------------
__global__ void select2_kernel() {
    int gw   = (blockIdx.x * blockDim.x + threadIdx.x) >> 5;
    int lane = threadIdx.x & 31;
    if (gw >= QN) return;

    const float4* row = (const float4*)(g_S + (size_t)gw * NPAD) + lane;

    float v[8]; int id[8];
#pragma unroll
    for (int s = 0; s < 8; s++) { v[s] = CUDART_INF_F; id[s] = 0x7fffffff; }
    float vmax = CUDART_INF_F;   // lex-max of the 8 (worst kept candidate)
    int   smax = 0, imax = 0x7fffffff;

#pragma unroll 1
    for (int j0 = 0; j0 < NPAD / 4; j0 += 32) {
        float4 x = __ldcs(&row[j0]);
        const int jb = (j0 + lane) * 4;
        float xv[4] = {x.x, x.y, x.z, x.w};
#pragma unroll
        for (int e = 0; e < 4; e++) {
            // strict <: scan is index-ascending, so ties keep the older (smaller) index
            if (xv[e] < vmax) {
                v[smax] = xv[e]; id[smax] = jb + e;
                vmax = v[0]; imax = id[0]; smax = 0;
#pragma unroll
                for (int s = 1; s < 8; s++)
                    if (v[s] > vmax || (v[s] == vmax && id[s] > imax)) {
                        vmax = v[s]; imax = id[s]; smax = s;
                    }
            }
        }
    }

    float* cvp = g_cv + (size_t)gw * CAND + lane * 8;
    int*   cip = g_ci + (size_t)gw * CAND + lane * 8;
#pragma unroll
    for (int s = 0; s < 8; s++) { cvp[s] = v[s]; cip[s] = id[s]; }
}

// ---------------------------------------------------------------------------
// Exact rescore: block/query, thread/candidate. fp32 dist = mm[i] - 2*q.m_i,
// then 32 rounds of block-wide lexicographic argmin; accumulate tv in order.
// ---------------------------------------------------------------------------
__global__ void __launch_bounds__(256)
rescore_kernel(const float* __restrict__ hq, const float* __restrict__ me,
               const float* __restrict__ tvals, float* __restrict__ out) {
    __shared__ float qs[DD];
    __shared__ float rv[8];
    __shared__ int   ri[8];
    __shared__ int   swi;
    __shared__ float ssum;

    const int qid = blockIdx.x, tid = threadIdx.x;
    const int lane = tid & 31, wid = tid >> 5;

    for (int i = tid; i < DD / 4; i += 256)
        ((float4*)qs)[i] = ((const float4*)(hq + (size_t)qid * DD))[i];
    if (tid == 0) ssum = 0.f;
    __syncthreads();

    const int myi = g_ci[(size_t)qid * CAND + tid];
    const float4* mrow = (const float4*)(me + (size_t)myi * DD);
    float acc = 0.f;
#pragma unroll 8
    for (int i = 0; i < DD / 4; i++) {
        float4 m  = __ldg(&mrow[i]);
        float4 qv = ((const float4*)qs)[i];
        acc = fmaf(m.x, qv.x, acc);
        acc = fmaf(m.y, qv.y, acc);
        acc = fmaf(m.z, qv.z, acc);
        acc = fmaf(m.w, qv.w, acc);
    }
    float mv = fmaf(-2.f, acc, g_mm[myi]);   // exact fp32 score
    int   mi = myi;                          // candidate indices unique per query

#pragma unroll 1
    for (int r = 0; r < KSEL; r++) {
        float wv = mv; int wi = mi;
#pragma unroll
        for (int o = 16; o; o >>= 1) {
            float ov = __shfl_xor_sync(0xffffffffu, wv, o);
            int   oi = __shfl_xor_sync(0xffffffffu, wi, o);
            if (ov < wv || (ov == wv && oi < wi)) { wv = ov; wi = oi; }
        }
        if (lane == 0) { rv[wid] = wv; ri[wid] = wi; }
        __syncthreads();
        if (tid == 0) {
            float bv = rv[0]; int bi = ri[0];
#pragma unroll
            for (int s = 1; s < 8; s++)
                if (rv[s] < bv || (rv[s] == bv && ri[s] < bi)) { bv = rv[s]; bi = ri[s]; }
            swi = bi;
            ssum += tvals[bi];
        }
        __syncthreads();
        if (mi == swi) mv = CUDART_INF_F;    // consume the winner
        __syncthreads();
    }
    if (tid == 0) out[qid] = ssum * (1.0f / KSEL);
}

// ---------------------------------------------------------------------------
extern "C" void kernel_launch(void* const* d_in, const int* in_sizes, int n_in,
                              void* d_out, int out_size) {
    const float* hq = (const float*)d_in[0];   // [2048, 512]
    const float* me = (const float*)d_in[1];   // [100000, 512]
    const float* tv = (const float*)d_in[2];   // [100000]
    float* out = (float*)d_out;                // [2048]

    convertA_kernel<<<(QN * (DD / 2) + 255) / 256, 256>>>(hq);
    convertB_kernel<<<(int)(((size_t)NPAD * (DD / 2) + 255) / 256), 256>>>(me);
    mm_kernel<<<NPAD / 8, 256>>>(me);

    cudaFuncSetAttribute(gemm_mma, cudaFuncAttributeMaxDynamicSharedMemorySize,
                         SMEM_TOTAL);
    // x-fast over M tiles: concurrent CTAs share B tiles in L2
    gemm_mma<<<dim3(QN / TILE_M, NPAD / TILE_N), 256, SMEM_TOTAL>>>();

    select2_kernel<<<QN / 8, 256>>>();

    rescore_kernel<<<QN, 256>>>(hq, me, tv, out);
}

// round 5
// speedup vs baseline: 4.1920x; 1.1121x over previous
#include <cuda_runtime.h>
#include <cuda_bf16.h>
#include <cuda_fp16.h>
#include <math_constants.h>
#include <cstdint>

// ---------------------------------------------------------------------------
// Problem constants
// ---------------------------------------------------------------------------
#define QN   2048
#define NN   100000
#define DD   512
#define NPAD 100096          // 782 * 128
#define KSEL 32
#define CAND 256             // shortlist size per query

// GEMM tiling (hi-only bf16): CTA 256x128, 8 warps (4M x 2N), warp 64x64
#define TILE_M 256
#define TILE_N 128
#define KC     64            // bf16 per K-chunk (128 B rows -> SW128 swizzle)
#define NCHUNK (DD / KC)     // 8
#define STAGES 3

#define OFF_A 0              // 256 rows x 128 B = 32 KB
#define OFF_B 32768          // 128 rows x 128 B = 16 KB
#define STAGE_BYTES 49152
#define SMEM_TOTAL (STAGES * STAGE_BYTES)   // 147456 -> 1 CTA/SM

// ---------------------------------------------------------------------------
// Scratch (device globals — no runtime allocation allowed)
// ---------------------------------------------------------------------------
__device__ float  g_mm[NPAD];                                   // ||m_j||^2; +INF for j >= NN
__device__ __half g_Sh[(size_t)QN * NPAD];                      // approx scores - 512, fp16 (~410 MB)
__device__ __align__(1024) __nv_bfloat16 g_A[QN * DD];          // hi(bf16) queries
__device__ __align__(1024) __nv_bfloat16 g_B[(size_t)NPAD * DD];// hi(bf16) memory
__device__ int g_ci[(size_t)QN * CAND];                         // shortlist indices

// ---------------------------------------------------------------------------
// PTX helpers (family-level sm_80+ features only)
// ---------------------------------------------------------------------------
__device__ __forceinline__ uint32_t smem_u32(const void* p) {
    uint32_t a;
    asm("{ .reg .u64 t; cvta.to.shared.u64 t, %1; cvt.u32.u64 %0, t; }"
        : "=r"(a) : "l"(p));
    return a;
}

#define CP_ASYNC16(dst, src) \
    asm volatile("cp.async.cg.shared.global [%0], [%1], 16;" \
                 :: "r"(dst), "l"(src) : "memory")
#define CP_COMMIT() asm volatile("cp.async.commit_group;" ::: "memory")
#define CP_WAIT2()  asm volatile("cp.async.wait_group 2;"  ::: "memory")

#define LDSM4(r, addr) \
    asm volatile("ldmatrix.sync.aligned.m8n8.x4.shared.b16 {%0,%1,%2,%3}, [%4];" \
                 : "=r"((r)[0]), "=r"((r)[1]), "=r"((r)[2]), "=r"((r)[3]) \
                 : "r"(addr))

#define MMA16816(c, a, b0, b1) \
    asm volatile("mma.sync.aligned.m16n8k16.row.col.f32.bf16.bf16.f32 " \
                 "{%0,%1,%2,%3}, {%4,%5,%6,%7}, {%8,%9}, {%0,%1,%2,%3};" \
                 : "+f"((c)[0]), "+f"((c)[1]), "+f"((c)[2]), "+f"((c)[3]) \
                 : "r"((a)[0]), "r"((a)[1]), "r"((a)[2]), "r"((a)[3]), \
                   "r"(b0), "r"(b1))

// ---------------------------------------------------------------------------
// fp32 -> bf16 hi conversion
// ---------------------------------------------------------------------------
__global__ void convertA_kernel(const float* __restrict__ X) {
    int i = blockIdx.x * blockDim.x + threadIdx.x;
    if (i >= QN * (DD / 2)) return;
    float2 x = ((const float2*)X)[i];
    ((__nv_bfloat162*)g_A)[i] =
        __nv_bfloat162(__float2bfloat16(x.x), __float2bfloat16(x.y));
}

__global__ void convertB_kernel(const float* __restrict__ X) {
    size_t i = (size_t)blockIdx.x * blockDim.x + threadIdx.x;
    if (i >= (size_t)NPAD * (DD / 2)) return;
    size_t row = (i * 2) >> 9;
    float2 x = make_float2(0.f, 0.f);
    if (row < NN) x = ((const float2*)X)[i];
    ((__nv_bfloat162*)g_B)[i] =
        __nv_bfloat162(__float2bfloat16(x.x), __float2bfloat16(x.y));
}

// ---------------------------------------------------------------------------
// ||m_j||^2 (fp32 exact); pad rows -> +INF so pad scores poison to +INF
// ---------------------------------------------------------------------------
__global__ void mm_kernel(const float* __restrict__ M) {
    int row  = blockIdx.x * 8 + (threadIdx.x >> 5);
    int lane = threadIdx.x & 31;
    if (row >= NPAD) return;
    if (row >= NN) { if (lane == 0) g_mm[row] = CUDART_INF_F; return; }
    const float4* p = (const float4*)(M + (size_t)row * DD);
    float s = 0.f;
#pragma unroll
    for (int i = 0; i < 4; i++) {
        float4 v = p[lane + 32 * i];
        s += v.x * v.x + v.y * v.y + v.z * v.z + v.w * v.w;
    }
#pragma unroll
    for (int o = 16; o; o >>= 1) s += __shfl_xor_sync(0xffffffffu, s, o);
    if (lane == 0) g_mm[row] = s;
}

// ---------------------------------------------------------------------------
// hi-only bf16 GEMM: S'[q][j] = (mm[j] - 2*dot_hi) - 512, stored fp16.
// CTA 256x128, 8 warps (4M x 2N), warp tile 64x64, 3-stage cp.async pipeline
// ---------------------------------------------------------------------------
__global__ void __launch_bounds__(256, 1)
gemm_mma() {
    extern __shared__ char smem[];
    const uint32_t sb = smem_u32(smem);
    const int tid  = threadIdx.x;
    const int lane = tid & 31, wid = tid >> 5;
    const int wm   = wid >> 1, wn = wid & 1;     // 4 x 2 warp grid
    const int gm   = blockIdx.x, gn = blockIdx.y;

    // cp.async mapping: thread -> (16B chunk lc, row lr); A 8 row-groups, B 4
    const int lc = tid & 7;
    const int lr = tid >> 3;                     // 0..31
    const __nv_bfloat16* srcA = g_A + (size_t)(gm * TILE_M + lr) * DD + lc * 8;
    const __nv_bfloat16* srcB = g_B + (size_t)(gn * TILE_N + lr) * DD + lc * 8;
    const uint32_t dsw = (uint32_t)((lc ^ (lr & 7)) * 16) + (uint32_t)lr * 128;

    // ldmatrix lane geometry
    const int l15 = lane & 15, lh = lane >> 4, l7 = lane & 7;
    const uint32_t arow = (uint32_t)(wm * 64 + l15) * 128;
    const uint32_t brow = (uint32_t)(wn * 64 + l15) * 128;

    float acc[4][8][4];
#pragma unroll
    for (int f = 0; f < 4; f++)
#pragma unroll
        for (int n = 0; n < 8; n++)
#pragma unroll
            for (int r = 0; r < 4; r++) acc[f][n][r] = 0.f;

#pragma unroll 1
    for (int s = 0; s < STAGES; s++) {           // prologue
        uint32_t s0 = sb + s * STAGE_BYTES + dsw;
        size_t ko = (size_t)s * KC;
#pragma unroll
        for (int p = 0; p < 8; p++)
            CP_ASYNC16(s0 + OFF_A + p * 32 * 128, srcA + ko + (size_t)p * 32 * DD);
#pragma unroll
        for (int p = 0; p < 4; p++)
            CP_ASYNC16(s0 + OFF_B + p * 32 * 128, srcB + ko + (size_t)p * 32 * DD);
        CP_COMMIT();
    }

#pragma unroll 1
    for (int i = 0; i < NCHUNK; i++) {
        CP_WAIT2();
        __syncthreads();

        const int st = i % STAGES;
        const uint32_t aB = sb + st * STAGE_BYTES + OFF_A + arow;
        const uint32_t bB = sb + st * STAGE_BYTES + OFF_B + brow;

#pragma unroll
        for (int s = 0; s < 4; s++) {            // 4 k16 slices per chunk
            const uint32_t ksw = (uint32_t)(((2 * s + lh) ^ l7) * 16);
            uint32_t ah[4][4], bh[4][4];
#pragma unroll
            for (int f = 0; f < 4; f++) LDSM4(ah[f], aB + f * 2048 + ksw);
#pragma unroll
            for (int g = 0; g < 4; g++) LDSM4(bh[g], bB + g * 2048 + ksw);
#pragma unroll
            for (int f = 0; f < 4; f++)
#pragma unroll
                for (int n = 0; n < 8; n++) {
                    const int g = n >> 1, o = n & 1;
                    MMA16816(acc[f][n], ah[f], bh[g][o], bh[g][o + 2]);
                }
        }
        __syncthreads();

        if (i + STAGES < NCHUNK) {
            uint32_t s0 = sb + st * STAGE_BYTES + dsw;
            size_t ko = (size_t)(i + STAGES) * KC;
#pragma unroll
            for (int p = 0; p < 8; p++)
                CP_ASYNC16(s0 + OFF_A + p * 32 * 128, srcA + ko + (size_t)p * 32 * DD);
#pragma unroll
            for (int p = 0; p < 4; p++)
                CP_ASYNC16(s0 + OFF_B + p * 32 * 128, srcB + ko + (size_t)p * 32 * DD);
        }
        CP_COMMIT();   // empty tail groups keep wait_group 2 exact
    }

    // epilogue: fp16 store of (mm[j] - 2*dot) - 512
    const int r0 = gm * TILE_M + wm * 64 + (lane >> 2);
    const int c0 = gn * TILE_N + wn * 64 + (lane & 3) * 2;
#pragma unroll
    for (int n = 0; n < 8; n++) {
        const int j = c0 + n * 8;
        const float m0 = g_mm[j] - 512.f, m1 = g_mm[j + 1] - 512.f;
#pragma unroll
        for (int f = 0; f < 4; f++) {
            const int R0 = r0 + f * 16;
            float2 v0 = make_float2(fmaf(-2.f, acc[f][n][0], m0),
                                    fmaf(-2.f, acc[f][n][1], m1));
            float2 v1 = make_float2(fmaf(-2.f, acc[f][n][2], m0),
                                    fmaf(-2.f, acc[f][n][3], m1));
            *(__half2*)(g_Sh + (size_t)R0 * NPAD + j)       = __float22half2_rn(v0);
            *(__half2*)(g_Sh + (size_t)(R0 + 8) * NPAD + j) = __float22half2_rn(v1);
        }
    }
}

// ---------------------------------------------------------------------------
// Shortlist: one warp/query over fp16 scores; per-lane local top-8 (no warp
// sync in hot loop). Union of per-lane top-8 = 256 candidates.
// ---------------------------------------------------------------------------
__global__ void select2_kernel() {
    int gw   = (blockIdx.x * blockDim.x + threadIdx.x) >> 5;
    int lane = threadIdx.x & 31;
    if (gw >= QN) return;

    const uint4* row = (const uint4*)(g_Sh + (size_t)gw * NPAD) + lane;

    float v[8]; int id[8];
#pragma unroll
    for (int s = 0; s < 8; s++) { v[s] = CUDART_INF_F; id[s] = 0x7fffffff; }
    float vmax = CUDART_INF_F;
    int   smax = 0, imax = 0x7fffffff;

#pragma unroll 1
    for (int it = 0; it < NPAD / (8 * 32); it++) {     // 391 iterations
        uint4 x = __ldcs(&row[it * 32]);
        const int jb = (it * 32 + lane) * 8;
        float xv[8];
        {
            float2 f0 = __half22float2(*(__half2*)&x.x);
            float2 f1 = __half22float2(*(__half2*)&x.y);
            float2 f2 = __half22float2(*(__half2*)&x.z);
            float2 f3 = __half22float2(*(__half2*)&x.w);
            xv[0] = f0.x; xv[1] = f0.y; xv[2] = f1.x; xv[3] = f1.y;
            xv[4] = f2.x; xv[5] = f2.y; xv[6] = f3.x; xv[7] = f3.y;
        }
#pragma unroll
        for (int e = 0; e < 8; e++) {
            if (xv[e] < vmax) {       // strict <: ascending scan keeps older index
                v[smax] = xv[e]; id[smax] = jb + e;
                vmax = v[0]; imax = id[0]; smax = 0;
#pragma unroll
                for (int s = 1; s < 8; s++)
                    if (v[s] > vmax || (v[s] == vmax && id[s] > imax)) {
                        vmax = v[s]; imax = id[s]; smax = s;
                    }
            }
        }
    }

    int* cip = g_ci + (size_t)gw * CAND + lane * 8;
#pragma unroll
    for (int s = 0; s < 8; s++) cip[s] = id[s];
}

// ---------------------------------------------------------------------------
// Exact rescore: block/query. Warp-cooperative coalesced gather (32 lanes
// stream one candidate row), then 32 rounds block-wide lexicographic argmin.
// ---------------------------------------------------------------------------
__global__ void __launch_bounds__(256)
rescore_kernel(const float* __restrict__ hq, const float* __restrict__ me,
               const float* __restrict__ tvals, float* __restrict__ out) {
    __shared__ float qs[DD];
    __shared__ float scs[CAND];
    __shared__ float rv[8];
    __shared__ int   ri[8];
    __shared__ int   swi;
    __shared__ float ssum;

    const int qid = blockIdx.x, tid = threadIdx.x;
    const int lane = tid & 31, wid = tid >> 5;

    for (int i = tid; i < DD / 4; i += 256)
        ((float4*)qs)[i] = ((const float4*)(hq + (size_t)qid * DD))[i];
    if (tid == 0) ssum = 0.f;
    __syncthreads();

    // Phase 1: coalesced exact scores. Warp w covers candidates [32w, 32w+32).
    const int* cbase = g_ci + (size_t)qid * CAND + wid * 32;
#pragma unroll 1
    for (int c = 0; c < 32; c++) {
        const int cand = cbase[c];               // uniform load (broadcast)
        const float4* mr = (const float4*)(me + (size_t)cand * DD);
        float a = 0.f;
#pragma unroll
        for (int i = 0; i < 4; i++) {
            float4 m  = __ldg(&mr[lane + 32 * i]);
            float4 qv = ((const float4*)qs)[lane + 32 * i];
            a = fmaf(m.x, qv.x, a); a = fmaf(m.y, qv.y, a);
            a = fmaf(m.z, qv.z, a); a = fmaf(m.w, qv.w, a);
        }
#pragma unroll
        for (int o = 16; o; o >>= 1) a += __shfl_xor_sync(0xffffffffu, a, o);
        if (lane == 0) scs[wid * 32 + c] = fmaf(-2.f, a, g_mm[cand]);
    }
    __syncthreads();

    // Phase 2: 32 rounds of lexicographic argmin (matches lax.top_k order)
    float mv = scs[tid];
    int   mi = g_ci[(size_t)qid * CAND + tid];   // unique per query

#pragma unroll 1
    for (int r = 0; r < KSEL; r++) {
        float wv = mv; int wi = mi;
#pragma unroll
        for (int o = 16; o; o >>= 1) {
            float ov = __shfl_xor_sync(0xffffffffu, wv, o);
            int   oi = __shfl_xor_sync(0xffffffffu, wi, o);
            if (ov < wv || (ov == wv && oi < wi)) { wv = ov; wi = oi; }
        }
        if (lane == 0) { rv[wid] = wv; ri[wid] = wi; }
        __syncthreads();
        if (tid == 0) {
            float bv = rv[0]; int bi = ri[0];
#pragma unroll
            for (int s = 1; s < 8; s++)
                if (rv[s] < bv || (rv[s] == bv && ri[s] < bi)) { bv = rv[s]; bi = ri[s]; }
            swi = bi;
            ssum += tvals[bi];
        }
        __syncthreads();
        if (mi == swi) mv = CUDART_INF_F;
        __syncthreads();
    }
    if (tid == 0) out[qid] = ssum * (1.0f / KSEL);
}

// ---------------------------------------------------------------------------
extern "C" void kernel_launch(void* const* d_in, const int* in_sizes, int n_in,
                              void* d_out, int out_size) {
    const float* hq = (const float*)d_in[0];   // [2048, 512]
    const float* me = (const float*)d_in[1];   // [100000, 512]
    const float* tv = (const float*)d_in[2];   // [100000]
    float* out = (float*)d_out;                // [2048]

    convertA_kernel<<<(QN * (DD / 2) + 255) / 256, 256>>>(hq);
    convertB_kernel<<<(int)(((size_t)NPAD * (DD / 2) + 255) / 256), 256>>>(me);
    mm_kernel<<<NPAD / 8, 256>>>(me);

    cudaFuncSetAttribute(gemm_mma, cudaFuncAttributeMaxDynamicSharedMemorySize,
                         SMEM_TOTAL);
    // x-fast over the 8 M-tiles: co-resident CTAs share B tiles in L2; A is L2-resident
    gemm_mma<<<dim3(QN / TILE_M, NPAD / TILE_N), 256, SMEM_TOTAL>>>();

    select2_kernel<<<QN / 8, 256>>>();

    rescore_kernel<<<QN, 256>>>(hq, me, tv, out);
}

// round 6
// speedup vs baseline: 5.0038x; 1.1936x over previous
#include <cuda_runtime.h>
#include <cuda_bf16.h>
#include <cuda_fp16.h>
#include <math_constants.h>
#include <cstdint>

// ---------------------------------------------------------------------------
// Problem constants
// ---------------------------------------------------------------------------
#define QN   2048
#define NN   100000
#define DD   512
#define NPAD 100096          // 782 * 128
#define KSEL 32
#define CAND 256             // shortlist size per query

// GEMM tiling (hi-only bf16): CTA 128x128, 8 warps (2M x 4N), warp 64x32
#define TILE_M 128
#define TILE_N 128
#define KC     64            // bf16 per K-chunk (128 B rows -> SW128 swizzle)
#define NCHUNK (DD / KC)     // 8
#define STAGES 3

#define OFF_A 0
#define OFF_B 16384
#define STAGE_BYTES 32768
#define SMEM_TOTAL (STAGES * STAGE_BYTES)   // 98304 -> 2 CTAs/SM

// ---------------------------------------------------------------------------
// Scratch (device globals — no runtime allocation allowed)
// ---------------------------------------------------------------------------
__device__ float  g_mm[NPAD];                                   // ||m_j||^2; +INF for j >= NN
__device__ __half g_Sh[(size_t)QN * NPAD];                      // approx scores - 512, fp16 (~410 MB)
__device__ __align__(1024) __nv_bfloat16 g_A[QN * DD];          // hi(bf16) queries
__device__ __align__(1024) __nv_bfloat16 g_B[(size_t)NPAD * DD];// hi(bf16) memory
__device__ int g_ci[(size_t)QN * CAND];                         // shortlist indices

// ---------------------------------------------------------------------------
// PTX helpers (family-level sm_80+ features only)
// ---------------------------------------------------------------------------
__device__ __forceinline__ uint32_t smem_u32(const void* p) {
    uint32_t a;
    asm("{ .reg .u64 t; cvta.to.shared.u64 t, %1; cvt.u32.u64 %0, t; }"
        : "=r"(a) : "l"(p));
    return a;
}

#define CP_ASYNC16(dst, src) \
    asm volatile("cp.async.cg.shared.global [%0], [%1], 16;" \
                 :: "r"(dst), "l"(src) : "memory")
#define CP_COMMIT() asm volatile("cp.async.commit_group;" ::: "memory")
#define CP_WAIT2()  asm volatile("cp.async.wait_group 2;"  ::: "memory")

#define LDSM4(r, addr) \
    asm volatile("ldmatrix.sync.aligned.m8n8.x4.shared.b16 {%0,%1,%2,%3}, [%4];" \
                 : "=r"((r)[0]), "=r"((r)[1]), "=r"((r)[2]), "=r"((r)[3]) \
                 : "r"(addr))

#define MMA16816(c, a, b0, b1) \
    asm volatile("mma.sync.aligned.m16n8k16.row.col.f32.bf16.bf16.f32 " \
                 "{%0,%1,%2,%3}, {%4,%5,%6,%7}, {%8,%9}, {%0,%1,%2,%3};" \
                 : "+f"((c)[0]), "+f"((c)[1]), "+f"((c)[2]), "+f"((c)[3]) \
                 : "r"((a)[0]), "r"((a)[1]), "r"((a)[2]), "r"((a)[3]), \
                   "r"(b0), "r"(b1))

// ---------------------------------------------------------------------------
// fp32 -> bf16 hi conversion for queries
// ---------------------------------------------------------------------------
__global__ void convertA_kernel(const float* __restrict__ X) {
    int i = blockIdx.x * blockDim.x + threadIdx.x;
    if (i >= QN * (DD / 2)) return;
    float2 x = ((const float2*)X)[i];
    ((__nv_bfloat162*)g_A)[i] =
        __nv_bfloat162(__float2bfloat16(x.x), __float2bfloat16(x.y));
}

// ---------------------------------------------------------------------------
// Fused: memory rows -> bf16 hi  AND  ||m_j||^2 (single pass over 205 MB).
// One warp per row; pad rows write zeros / +INF.
// ---------------------------------------------------------------------------
__global__ void convB_mm_kernel(const float* __restrict__ M) {
    int row  = blockIdx.x * 8 + (threadIdx.x >> 5);
    int lane = threadIdx.x & 31;
    if (row >= NPAD) return;
    __nv_bfloat162* dst = (__nv_bfloat162*)(g_B + (size_t)row * DD) + lane * 8;
    if (row >= NN) {
        if (lane == 0) g_mm[row] = CUDART_INF_F;
        __nv_bfloat162 z(__float2bfloat16(0.f), __float2bfloat16(0.f));
#pragma unroll
        for (int t = 0; t < 8; t++) dst[t] = z;
        return;
    }
    const float4* p = (const float4*)(M + (size_t)row * DD) + lane * 4;
    float s = 0.f;
#pragma unroll
    for (int i = 0; i < 4; i++) {
        float4 v = p[i];
        s += v.x * v.x + v.y * v.y + v.z * v.z + v.w * v.w;
        dst[2 * i + 0] = __nv_bfloat162(__float2bfloat16(v.x), __float2bfloat16(v.y));
        dst[2 * i + 1] = __nv_bfloat162(__float2bfloat16(v.z), __float2bfloat16(v.w));
    }
#pragma unroll
    for (int o = 16; o; o >>= 1) s += __shfl_xor_sync(0xffffffffu, s, o);
    if (lane == 0) g_mm[row] = s;
}

// ---------------------------------------------------------------------------
// hi-only bf16 GEMM: S'[q][j] = (mm[j] - 2*dot_hi) - 512, stored fp16.
// CTA 128x128, 8 warps (2M x 4N), warp 64x32, 3-stage pipeline, 2 CTAs/SM.
// ---------------------------------------------------------------------------
__global__ void __launch_bounds__(256, 2)
gemm_mma() {
    extern __shared__ char smem[];
    const uint32_t sb = smem_u32(smem);
    const int tid  = threadIdx.x;
    const int lane = tid & 31, wid = tid >> 5;
    const int wm   = wid >> 2, wn = wid & 3;     // 2 x 4 warp grid
    const int gm   = blockIdx.x, gn = blockIdx.y;

    // cp.async mapping: thread -> (16B chunk lc, row lr), 4 row-groups
    const int lc = tid & 7;
    const int lr = tid >> 3;                     // 0..31
    const __nv_bfloat16* srcA = g_A + (size_t)(gm * TILE_M + lr) * DD + lc * 8;
    const __nv_bfloat16* srcB = g_B + (size_t)(gn * TILE_N + lr) * DD + lc * 8;
    const uint32_t dsw = (uint32_t)((lc ^ (lr & 7)) * 16) + (uint32_t)lr * 128;

    // ldmatrix lane geometry
    const int l15 = lane & 15, lh = lane >> 4, l7 = lane & 7;
    const uint32_t arow = (uint32_t)(wm * 64 + l15) * 128;
    const uint32_t brow = (uint32_t)(wn * 32 + l15) * 128;

    float acc[4][4][4];
#pragma unroll
    for (int f = 0; f < 4; f++)
#pragma unroll
        for (int n = 0; n < 4; n++)
#pragma unroll
            for (int r = 0; r < 4; r++) acc[f][n][r] = 0.f;

#pragma unroll 1
    for (int s = 0; s < STAGES; s++) {           // prologue
        uint32_t s0 = sb + s * STAGE_BYTES + dsw;
        size_t ko = (size_t)s * KC;
#pragma unroll
        for (int p = 0; p < 4; p++) {
            uint32_t d = s0 + p * 32 * 128;
            CP_ASYNC16(d + OFF_A, srcA + ko + (size_t)p * 32 * DD);
            CP_ASYNC16(d + OFF_B, srcB + ko + (size_t)p * 32 * DD);
        }
        CP_COMMIT();
    }

#pragma unroll 1
    for (int i = 0; i < NCHUNK; i++) {
        CP_WAIT2();
        __syncthreads();

        const int st = i % STAGES;
        const uint32_t aB = sb + st * STAGE_BYTES + OFF_A + arow;
        const uint32_t bB = sb + st * STAGE_BYTES + OFF_B + brow;

#pragma unroll
        for (int s = 0; s < 4; s++) {            // 4 k16 slices per chunk
            const uint32_t ksw = (uint32_t)(((2 * s + lh) ^ l7) * 16);
            uint32_t ah[4][4], bh[2][4];
#pragma unroll
            for (int f = 0; f < 4; f++) LDSM4(ah[f], aB + f * 2048 + ksw);
#pragma unroll
            for (int g = 0; g < 2; g++) LDSM4(bh[g], bB + g * 2048 + ksw);
#pragma unroll
            for (int f = 0; f < 4; f++)
#pragma unroll
                for (int n = 0; n < 4; n++) {
                    const int g = n >> 1, o = n & 1;
                    MMA16816(acc[f][n], ah[f], bh[g][o], bh[g][o + 2]);
                }
        }
        __syncthreads();

        if (i + STAGES < NCHUNK) {
            uint32_t s0 = sb + st * STAGE_BYTES + dsw;
            size_t ko = (size_t)(i + STAGES) * KC;
#pragma unroll
            for (int p = 0; p < 4; p++) {
                uint32_t d = s0 + p * 32 * 128;
                CP_ASYNC16(d + OFF_A, srcA + ko + (size_t)p * 32 * DD);
                CP_ASYNC16(d + OFF_B, srcB + ko + (size_t)p * 32 * DD);
            }
        }
        CP_COMMIT();   // empty tail groups keep wait_group 2 exact
    }

    // epilogue: fp16 store of (mm[j] - 2*dot) - 512
    const int r0 = gm * TILE_M + wm * 64 + (lane >> 2);
    const int c0 = gn * TILE_N + wn * 32 + (lane & 3) * 2;
#pragma unroll
    for (int n = 0; n < 4; n++) {
        const int j = c0 + n * 8;
        const float m0 = g_mm[j] - 512.f, m1 = g_mm[j + 1] - 512.f;
#pragma unroll
        for (int f = 0; f < 4; f++) {
            const int R0 = r0 + f * 16;
            float2 v0 = make_float2(fmaf(-2.f, acc[f][n][0], m0),
                                    fmaf(-2.f, acc[f][n][1], m1));
            float2 v1 = make_float2(fmaf(-2.f, acc[f][n][2], m0),
                                    fmaf(-2.f, acc[f][n][3], m1));
            *(__half2*)(g_Sh + (size_t)R0 * NPAD + j)       = __float22half2_rn(v0);
            *(__half2*)(g_Sh + (size_t)(R0 + 8) * NPAD + j) = __float22half2_rn(v1);
        }
    }
}

// ---------------------------------------------------------------------------
// Shortlist: one warp/query over fp16 scores; per-lane local top-8.
// ---------------------------------------------------------------------------
__global__ void select2_kernel() {
    int gw   = (blockIdx.x * blockDim.x + threadIdx.x) >> 5;
    int lane = threadIdx.x & 31;
    if (gw >= QN) return;

    const uint4* row = (const uint4*)(g_Sh + (size_t)gw * NPAD) + lane;

    float v[8]; int id[8];
#pragma unroll
    for (int s = 0; s < 8; s++) { v[s] = CUDART_INF_F; id[s] = 0x7fffffff; }
    float vmax = CUDART_INF_F;
    int   smax = 0, imax = 0x7fffffff;

#pragma unroll 1
    for (int it = 0; it < NPAD / (8 * 32); it++) {     // 391 iterations
        uint4 x = __ldcs(&row[it * 32]);
        const int jb = (it * 32 + lane) * 8;
        float xv[8];
        {
            float2 f0 = __half22float2(*(__half2*)&x.x);
            float2 f1 = __half22float2(*(__half2*)&x.y);
            float2 f2 = __half22float2(*(__half2*)&x.z);
            float2 f3 = __half22float2(*(__half2*)&x.w);
            xv[0] = f0.x; xv[1] = f0.y; xv[2] = f1.x; xv[3] = f1.y;
            xv[4] = f2.x; xv[5] = f2.y; xv[6] = f3.x; xv[7] = f3.y;
        }
#pragma unroll
        for (int e = 0; e < 8; e++) {
            if (xv[e] < vmax) {       // strict <: ascending scan keeps older index
                v[smax] = xv[e]; id[smax] = jb + e;
                vmax = v[0]; imax = id[0]; smax = 0;
#pragma unroll
                for (int s = 1; s < 8; s++)
                    if (v[s] > vmax || (v[s] == vmax && id[s] > imax)) {
                        vmax = v[s]; imax = id[s]; smax = s;
                    }
            }
        }
    }

    int* cip = g_ci + (size_t)gw * CAND + lane * 8;
#pragma unroll
    for (int s = 0; s < 8; s++) cip[s] = id[s];
}

// ---------------------------------------------------------------------------
// Exact rescore: block/query, warp-cooperative coalesced gather, then
// 32 rounds of block-wide lexicographic argmin (lax.top_k tie-break order).
// ---------------------------------------------------------------------------
__global__ void __launch_bounds__(256)
rescore_kernel(const float* __restrict__ hq, const float* __restrict__ me,
               const float* __restrict__ tvals, float* __restrict__ out) {
    __shared__ float qs[DD];
    __shared__ float scs[CAND];
    __shared__ float rv[8];
    __shared__ int   ri[8];
    __shared__ int   swi;
    __shared__ float ssum;

    const int qid = blockIdx.x, tid = threadIdx.x;
    const int lane = tid & 31, wid = tid >> 5;

    for (int i = tid; i < DD / 4; i += 256)
        ((float4*)qs)[i] = ((const float4*)(hq + (size_t)qid * DD))[i];
    if (tid == 0) ssum = 0.f;
    __syncthreads();

    // Phase 1: coalesced exact fp32 scores; warp w covers candidates [32w, 32w+32)
    const int* cbase = g_ci + (size_t)qid * CAND + wid * 32;
#pragma unroll 1
    for (int c = 0; c < 32; c++) {
        const int cand = cbase[c];               // uniform (broadcast) load
        const float4* mr = (const float4*)(me + (size_t)cand * DD);
        float a = 0.f;
#pragma unroll
        for (int i = 0; i < 4; i++) {
            float4 m  = __ldg(&mr[lane + 32 * i]);
            float4 qv = ((const float4*)qs)[lane + 32 * i];
            a = fmaf(m.x, qv.x, a); a = fmaf(m.y, qv.y, a);
            a = fmaf(m.z, qv.z, a); a = fmaf(m.w, qv.w, a);
        }
#pragma unroll
        for (int o = 16; o; o >>= 1) a += __shfl_xor_sync(0xffffffffu, a, o);
        if (lane == 0) scs[wid * 32 + c] = fmaf(-2.f, a, g_mm[cand]);
    }
    __syncthreads();

    // Phase 2: 32 rounds of lexicographic argmin
    float mv = scs[tid];
    int   mi = g_ci[(size_t)qid * CAND + tid];

#pragma unroll 1
    for (int r = 0; r < KSEL; r++) {
        float wv = mv; int wi = mi;
#pragma unroll
        for (int o = 16; o; o >>= 1) {
            float ov = __shfl_xor_sync(0xffffffffu, wv, o);
            int   oi = __shfl_xor_sync(0xffffffffu, wi, o);
            if (ov < wv || (ov == wv && oi < wi)) { wv = ov; wi = oi; }
        }
        if (lane == 0) { rv[wid] = wv; ri[wid] = wi; }
        __syncthreads();
        if (tid == 0) {
            float bv = rv[0]; int bi = ri[0];
#pragma unroll
            for (int s = 1; s < 8; s++)
                if (rv[s] < bv || (rv[s] == bv && ri[s] < bi)) { bv = rv[s]; bi = ri[s]; }
            swi = bi;
            ssum += tvals[bi];
        }
        __syncthreads();
        if (mi == swi) mv = CUDART_INF_F;
        __syncthreads();
    }
    if (tid == 0) out[qid] = ssum * (1.0f / KSEL);
}

// ---------------------------------------------------------------------------
extern "C" void kernel_launch(void* const* d_in, const int* in_sizes, int n_in,
                              void* d_out, int out_size) {
    const float* hq = (const float*)d_in[0];   // [2048, 512]
    const float* me = (const float*)d_in[1];   // [100000, 512]
    const float* tv = (const float*)d_in[2];   // [100000]
    float* out = (float*)d_out;                // [2048]

    convertA_kernel<<<(QN * (DD / 2) + 255) / 256, 256>>>(hq);
    convB_mm_kernel<<<NPAD / 8, 256>>>(me);    // fused convert + norms

    cudaFuncSetAttribute(gemm_mma, cudaFuncAttributeMaxDynamicSharedMemorySize,
                         SMEM_TOTAL);
    // x-fast over the 16 M-tiles: co-resident CTAs share B tiles in L2
    gemm_mma<<<dim3(QN / TILE_M, NPAD / TILE_N), 256, SMEM_TOTAL>>>();

    select2_kernel<<<QN / 8, 256>>>();

    rescore_kernel<<<QN, 256>>>(hq, me, tv, out);
}